// round 1
// baseline (speedup 1.0000x reference)
#include <cuda_runtime.h>
#include <cuda_bf16.h>

// Problem constants
#define BATCH     4
#define SEQ       1024
#define EMB       1024
#define NHEADS    16
#define HDIM      64
#define QKV_COLS  (3 * NHEADS * HDIM)   // 3072
#define ROWS      (BATCH * SEQ)         // 4096

// Scratch (allocation-free rule: __device__ globals)
__device__ float g_qkv[ROWS * QKV_COLS];      // 4096 x 3072
__device__ float g_att[ROWS * EMB];           // 4096 x 1024

// ---------------------------------------------------------------------------
// Tiled fp32 GEMM with fused bias: C[M,N] = A[M,K] @ B[K,N] + bias[N]
// BM=BN=128, BK=16, 256 threads, 8x8 microtile. M,N,K divisible by tiles.
// ---------------------------------------------------------------------------
#define BM 128
#define BN 128
#define BK 16
#define TM 8
#define TN 8

__global__ __launch_bounds__(256) void sgemm_bias(
    int M, int N, int K,
    const float* __restrict__ A,
    const float* __restrict__ B,
    const float* __restrict__ bias,
    float* __restrict__ C)
{
    __shared__ float As[BK][BM];
    __shared__ float Bs[BK][BN];

    const int t = threadIdx.x;
    const int cRow = blockIdx.y;
    const int cCol = blockIdx.x;

    const int threadRow = t / (BN / TN);   // 0..15
    const int threadCol = t % (BN / TN);   // 0..15

    const float* Ab = A + (size_t)cRow * BM * K;
    const float* Bb = B + (size_t)cCol * BN;
    float*       Cb = C + (size_t)cRow * BM * N + (size_t)cCol * BN;

    const int innerRowA = t / (BK / 4);    // 0..63
    const int innerColA = t % (BK / 4);    // 0..3
    const int innerRowB = t / (BN / 4);    // 0..7
    const int innerColB = t % (BN / 4);    // 0..31

    float acc[TM][TN];
    #pragma unroll
    for (int i = 0; i < TM; i++)
        #pragma unroll
        for (int j = 0; j < TN; j++)
            acc[i][j] = 0.0f;

    float regM[TM], regN[TN];

    for (int k0 = 0; k0 < K; k0 += BK) {
        // Load A tile (BM x BK), stored transposed for contiguous compute reads
        #pragma unroll
        for (int i = 0; i < 2; i++) {
            int r = innerRowA + i * 64;
            float4 v = *reinterpret_cast<const float4*>(&Ab[(size_t)r * K + innerColA * 4]);
            As[innerColA * 4 + 0][r] = v.x;
            As[innerColA * 4 + 1][r] = v.y;
            As[innerColA * 4 + 2][r] = v.z;
            As[innerColA * 4 + 3][r] = v.w;
        }
        // Load B tile (BK x BN)
        #pragma unroll
        for (int i = 0; i < 2; i++) {
            int r = innerRowB + i * 8;
            *reinterpret_cast<float4*>(&Bs[r][innerColB * 4]) =
                *reinterpret_cast<const float4*>(&Bb[(size_t)r * N + innerColB * 4]);
        }
        __syncthreads();
        Ab += BK;
        Bb += (size_t)BK * N;

        #pragma unroll
        for (int k = 0; k < BK; k++) {
            #pragma unroll
            for (int i = 0; i < TM; i++) regM[i] = As[k][threadRow * TM + i];
            #pragma unroll
            for (int j = 0; j < TN; j++) regN[j] = Bs[k][threadCol * TN + j];
            #pragma unroll
            for (int i = 0; i < TM; i++)
                #pragma unroll
                for (int j = 0; j < TN; j++)
                    acc[i][j] += regM[i] * regN[j];
        }
        __syncthreads();
    }

    // Epilogue: add bias, vectorized stores
    #pragma unroll
    for (int i = 0; i < TM; i++) {
        int row = threadRow * TM + i;
        #pragma unroll
        for (int j = 0; j < TN; j += 4) {
            int col = threadCol * TN + j;
            float4 bv = *reinterpret_cast<const float4*>(&bias[cCol * BN + col]);
            float4 v;
            v.x = acc[i][j + 0] + bv.x;
            v.y = acc[i][j + 1] + bv.y;
            v.z = acc[i][j + 2] + bv.z;
            v.w = acc[i][j + 3] + bv.w;
            *reinterpret_cast<float4*>(&Cb[(size_t)row * N + col]) = v;
        }
    }
}

// ---------------------------------------------------------------------------
// Attention: for each (b, h), softmax(Q K^T / 8) V.
// One thread = one query row. Streams K/V in 64-key tiles through smem.
// No max-subtraction: |scores| <= |q||k|/8 ~ O(8), exp() safe in fp32.
// qkv layout per row (b*SEQ+n): [0:1024)=K, [1024:2048)=Q, [2048:3072)=V,
// head h occupies columns h*64 .. h*64+63 within each third.
// Writes g_att row-major (row = b*SEQ+n, col = h*64+d).
// ---------------------------------------------------------------------------
#define KT 64   // keys per smem tile
#define QT 128  // query rows per block (= blockDim.x)

__global__ __launch_bounds__(QT) void attn_kernel()
{
    __shared__ float Ks[KT * HDIM];
    __shared__ float Vs[KT * HDIM];

    const int bh = blockIdx.y;
    const int b  = bh >> 4;          // / NHEADS
    const int h  = bh & 15;          // % NHEADS
    const int n  = blockIdx.x * QT + threadIdx.x;

    const size_t rowBase = ((size_t)b * SEQ + n) * QKV_COLS;
    const int    hoff    = h * HDIM;

    // Load pre-scaled q into registers
    float q[HDIM];
    {
        const float* qp = g_qkv + rowBase + EMB + hoff;   // Q third
        #pragma unroll
        for (int d = 0; d < HDIM; d++) q[d] = qp[d] * 0.125f;
    }

    float o[HDIM];
    #pragma unroll
    for (int d = 0; d < HDIM; d++) o[d] = 0.0f;
    float l = 0.0f;

    const size_t kvRow0 = (size_t)b * SEQ * QKV_COLS;

    for (int kt = 0; kt < SEQ / KT; kt++) {
        // Cooperative load of K and V tiles (float4 granularity)
        for (int e = threadIdx.x; e < KT * HDIM / 4; e += QT) {
            int r  = e >> 4;          // key row within tile (HDIM/4 = 16 float4 per row)
            int c4 = e & 15;
            size_t src = kvRow0 + (size_t)(kt * KT + r) * QKV_COLS + hoff + c4 * 4;
            reinterpret_cast<float4*>(Ks)[e] =
                *reinterpret_cast<const float4*>(&g_qkv[src]);            // K third (offset 0)
            reinterpret_cast<float4*>(Vs)[e] =
                *reinterpret_cast<const float4*>(&g_qkv[src + 2 * EMB]);  // V third
        }
        __syncthreads();

        for (int j = 0; j < KT; j++) {
            const float* kr = &Ks[j * HDIM];
            float s = 0.0f;
            #pragma unroll
            for (int d = 0; d < HDIM; d++) s += q[d] * kr[d];
            float p = __expf(s);
            l += p;
            const float* vr = &Vs[j * HDIM];
            #pragma unroll
            for (int d = 0; d < HDIM; d++) o[d] += p * vr[d];
        }
        __syncthreads();
    }

    const float inv = 1.0f / l;
    float* outp = g_att + ((size_t)b * SEQ + n) * EMB + hoff;
    #pragma unroll
    for (int d = 0; d < HDIM; d += 4) {
        float4 v;
        v.x = o[d + 0] * inv;
        v.y = o[d + 1] * inv;
        v.z = o[d + 2] * inv;
        v.w = o[d + 3] * inv;
        *reinterpret_cast<float4*>(&outp[d]) = v;
    }
}

// ---------------------------------------------------------------------------
// Launch: inputs in order x, W_qkv, b_qkv, W_out, b_out
// ---------------------------------------------------------------------------
extern "C" void kernel_launch(void* const* d_in, const int* in_sizes, int n_in,
                              void* d_out, int out_size)
{
    const float* x     = (const float*)d_in[0];
    const float* W_qkv = (const float*)d_in[1];
    const float* b_qkv = (const float*)d_in[2];
    const float* W_out = (const float*)d_in[3];
    const float* b_out = (const float*)d_in[4];
    float*       out   = (float*)d_out;

    float* qkv_ptr = nullptr;
    float* att_ptr = nullptr;
    cudaGetSymbolAddress((void**)&qkv_ptr, g_qkv);
    cudaGetSymbolAddress((void**)&att_ptr, g_att);

    // 1) QKV projection: [4096,1024] @ [1024,3072] + b
    {
        dim3 grid(QKV_COLS / BN, ROWS / BM);   // (24, 32)
        sgemm_bias<<<grid, 256>>>(ROWS, QKV_COLS, EMB, x, W_qkv, b_qkv, qkv_ptr);
    }

    // 2) Attention
    {
        dim3 grid(SEQ / QT, BATCH * NHEADS);   // (8, 64)
        attn_kernel<<<grid, QT>>>();
    }

    // 3) Output projection: [4096,1024] @ [1024,1024] + b
    {
        dim3 grid(EMB / BN, ROWS / BM);        // (8, 32)
        sgemm_bias<<<grid, 256>>>(ROWS, EMB, EMB, att_ptr, W_out, b_out, out);
    }
}

// round 2
// speedup vs baseline: 1.7356x; 1.7356x over previous
#include <cuda_runtime.h>
#include <cuda_bf16.h>
#include <cstdint>

// Problem constants
#define BATCH     4
#define SEQ       1024
#define EMB       1024
#define NHEADS    16
#define HDIM      64
#define QKV_COLS  (3 * NHEADS * HDIM)   // 3072
#define ROWS      (BATCH * SEQ)         // 4096

// Scratch (allocation-free rule: __device__ globals)
__device__ float g_qkv[ROWS * QKV_COLS];      // 4096 x 3072
__device__ float g_att[ROWS * EMB];           // 4096 x 1024

// ===========================================================================
// TF32 mma.sync GEMM with fused bias: C = A[M,K] @ B[K,N] + bias
// CTA tile 128x128x32, 8 warps (2x4), warp tile 64x32 via m16n8k8.
// Smem strides chosen for conflict-free scalar fragment loads:
//   A stride 36  (36 % 32 == 4  -> bank = 4*grp + qid, distinct)
//   B stride 136 (136 % 32 == 8 -> bank = 8*qid + grp, distinct)
// ===========================================================================
#define GBM 128
#define GBN 128
#define GBK 32
#define ASTRIDE 36
#define BSTRIDE 136
#define GEMM_SMEM ((2*GBM*ASTRIDE + 2*GBK*BSTRIDE) * 4)   // 71680 bytes

__device__ __forceinline__ uint32_t f2tf32(float x) {
    uint32_t u;
    asm("cvt.rna.tf32.f32 %0, %1;" : "=r"(u) : "f"(x));
    return u;
}

__device__ __forceinline__ void mma_tf32(float c[4], const uint32_t a[4], const uint32_t b[2]) {
    asm volatile(
        "mma.sync.aligned.m16n8k8.row.col.f32.tf32.tf32.f32 "
        "{%0,%1,%2,%3},{%4,%5,%6,%7},{%8,%9},{%0,%1,%2,%3};"
        : "+f"(c[0]), "+f"(c[1]), "+f"(c[2]), "+f"(c[3])
        : "r"(a[0]), "r"(a[1]), "r"(a[2]), "r"(a[3]), "r"(b[0]), "r"(b[1]));
}

__global__ __launch_bounds__(256, 1) void mma_gemm_bias(
    int M, int N, int K,
    const float* __restrict__ A,
    const float* __restrict__ B,
    const float* __restrict__ bias,
    float* __restrict__ C)
{
    extern __shared__ uint32_t sm[];
    uint32_t* As = sm;                         // [2][GBM][ASTRIDE]
    uint32_t* Bs = sm + 2 * GBM * ASTRIDE;     // [2][GBK][BSTRIDE]

    const int t    = threadIdx.x;
    const int lane = t & 31;
    const int warp = t >> 5;
    const int wm   = warp >> 2;   // 0..1
    const int wn   = warp & 3;    // 0..3
    const int grp  = lane >> 2;   // 0..7
    const int qid  = lane & 3;    // 0..3

    const int bm = blockIdx.y * GBM;
    const int bn = blockIdx.x * GBN;

    // staging indices
    const int arow = t >> 3;          // 0..31, + p*32
    const int acol = (t & 7) * 4;     // 0..28
    const int brow = t >> 5;          // 0..7,  + p*8
    const int bcol = (t & 31) * 4;    // 0..124

    float4 pa[4], pb[4];

    // prologue: load k-tile 0
    {
        const float* Ag = A + (size_t)bm * K;
        const float* Bg = B + bn;
        #pragma unroll
        for (int p = 0; p < 4; p++)
            pa[p] = *(const float4*)&Ag[(size_t)(arow + p * 32) * K + acol];
        #pragma unroll
        for (int p = 0; p < 4; p++)
            pb[p] = *(const float4*)&Bg[(size_t)(brow + p * 8) * N + bcol];
    }

    float c[4][4][4];
    #pragma unroll
    for (int mi = 0; mi < 4; mi++)
        #pragma unroll
        for (int ni = 0; ni < 4; ni++)
            #pragma unroll
            for (int r = 0; r < 4; r++)
                c[mi][ni][r] = 0.0f;

    // store tile to buffer (with tf32 rounding)
    auto sts_tile = [&](int buf) {
        uint32_t* Ab = As + buf * GBM * ASTRIDE;
        uint32_t* Bb = Bs + buf * GBK * BSTRIDE;
        #pragma unroll
        for (int p = 0; p < 4; p++) {
            uint4 v;
            v.x = f2tf32(pa[p].x); v.y = f2tf32(pa[p].y);
            v.z = f2tf32(pa[p].z); v.w = f2tf32(pa[p].w);
            *(uint4*)&Ab[(arow + p * 32) * ASTRIDE + acol] = v;
        }
        #pragma unroll
        for (int p = 0; p < 4; p++) {
            uint4 v;
            v.x = f2tf32(pb[p].x); v.y = f2tf32(pb[p].y);
            v.z = f2tf32(pb[p].z); v.w = f2tf32(pb[p].w);
            *(uint4*)&Bb[(brow + p * 8) * BSTRIDE + bcol] = v;
        }
    };

    sts_tile(0);
    __syncthreads();

    const int NT = K / GBK;
    for (int kt = 0; kt < NT; kt++) {
        const int cur = kt & 1;

        // prefetch next tile into registers
        if (kt + 1 < NT) {
            const int k0 = (kt + 1) * GBK;
            const float* Ag = A + (size_t)bm * K + k0;
            const float* Bg = B + (size_t)k0 * N + bn;
            #pragma unroll
            for (int p = 0; p < 4; p++)
                pa[p] = *(const float4*)&Ag[(size_t)(arow + p * 32) * K + acol];
            #pragma unroll
            for (int p = 0; p < 4; p++)
                pb[p] = *(const float4*)&Bg[(size_t)(brow + p * 8) * N + bcol];
        }

        // compute on buffer cur
        const uint32_t* Ab = As + cur * GBM * ASTRIDE + (wm * 64) * ASTRIDE;
        const uint32_t* Bb = Bs + cur * GBK * BSTRIDE + wn * 32;

        #pragma unroll
        for (int ks = 0; ks < 4; ks++) {
            const int kb = ks * 8;
            uint32_t af[4][4], bf[4][2];
            #pragma unroll
            for (int mi = 0; mi < 4; mi++) {
                const uint32_t* ap = Ab + (mi * 16 + grp) * ASTRIDE + kb + qid;
                af[mi][0] = ap[0];
                af[mi][1] = ap[8 * ASTRIDE];
                af[mi][2] = ap[4];
                af[mi][3] = ap[8 * ASTRIDE + 4];
            }
            #pragma unroll
            for (int ni = 0; ni < 4; ni++) {
                const uint32_t* bp = Bb + (kb + qid) * BSTRIDE + ni * 8 + grp;
                bf[ni][0] = bp[0];
                bf[ni][1] = bp[4 * BSTRIDE];
            }
            #pragma unroll
            for (int mi = 0; mi < 4; mi++)
                #pragma unroll
                for (int ni = 0; ni < 4; ni++)
                    mma_tf32(c[mi][ni], af[mi], bf[ni]);
        }

        if (kt + 1 < NT) sts_tile(cur ^ 1);
        __syncthreads();
    }

    // epilogue: bias + store
    #pragma unroll
    for (int mi = 0; mi < 4; mi++) {
        const int r0 = bm + wm * 64 + mi * 16 + grp;
        #pragma unroll
        for (int ni = 0; ni < 4; ni++) {
            const int col = bn + wn * 32 + ni * 8 + qid * 2;
            float2 bv = *(const float2*)&bias[col];
            float2 v0, v1;
            v0.x = c[mi][ni][0] + bv.x;  v0.y = c[mi][ni][1] + bv.y;
            v1.x = c[mi][ni][2] + bv.x;  v1.y = c[mi][ni][3] + bv.y;
            *(float2*)&C[(size_t)r0 * N + col]       = v0;
            *(float2*)&C[(size_t)(r0 + 8) * N + col] = v1;
        }
    }
}

// ===========================================================================
// Attention with packed f32x2 FMA: softmax(Q K^T / 8) V per (b,h).
// One thread = one query row; K/V streamed via smem in 64-key tiles.
// qkv row layout: [0:1024)=K, [1024:2048)=Q, [2048:3072)=V.
// ===========================================================================
#define KT 64
#define QT 128

typedef unsigned long long u64;

__device__ __forceinline__ u64 pk2(float lo, float hi) {
    u64 r; asm("mov.b64 %0,{%1,%2};" : "=l"(r) : "f"(lo), "f"(hi)); return r;
}
__device__ __forceinline__ void upk2(u64 v, float& lo, float& hi) {
    asm("mov.b64 {%0,%1},%2;" : "=f"(lo), "=f"(hi) : "l"(v));
}
__device__ __forceinline__ u64 ffma2(u64 a, u64 b, u64 c) {
    u64 d; asm("fma.rn.f32x2 %0,%1,%2,%3;" : "=l"(d) : "l"(a), "l"(b), "l"(c)); return d;
}

__global__ __launch_bounds__(QT) void attn_kernel()
{
    __shared__ __align__(16) float Ks[KT * HDIM];
    __shared__ __align__(16) float Vs[KT * HDIM];

    const int bh = blockIdx.y;
    const int b  = bh >> 4;
    const int h  = bh & 15;
    const int n  = blockIdx.x * QT + threadIdx.x;

    const size_t rowBase = ((size_t)b * SEQ + n) * QKV_COLS;
    const int    hoff    = h * HDIM;

    // Load pre-scaled q, packed into f32x2
    u64 q2[HDIM / 2];
    {
        const float* qp = g_qkv + rowBase + EMB + hoff;   // Q third
        #pragma unroll
        for (int d = 0; d < HDIM; d += 4) {
            float4 v = *(const float4*)&qp[d];
            q2[d / 2 + 0] = pk2(v.x * 0.125f, v.y * 0.125f);
            q2[d / 2 + 1] = pk2(v.z * 0.125f, v.w * 0.125f);
        }
    }

    u64 o2[HDIM / 2];
    #pragma unroll
    for (int i = 0; i < HDIM / 2; i++) o2[i] = 0ull;
    float l = 0.0f;

    const size_t kvRow0 = (size_t)b * SEQ * QKV_COLS;

    for (int kt = 0; kt < SEQ / KT; kt++) {
        // cooperative K/V tile load
        for (int e = threadIdx.x; e < KT * HDIM / 4; e += QT) {
            int r  = e >> 4;
            int c4 = e & 15;
            size_t src = kvRow0 + (size_t)(kt * KT + r) * QKV_COLS + hoff + c4 * 4;
            reinterpret_cast<float4*>(Ks)[e] =
                *reinterpret_cast<const float4*>(&g_qkv[src]);            // K third
            reinterpret_cast<float4*>(Vs)[e] =
                *reinterpret_cast<const float4*>(&g_qkv[src + 2 * EMB]);  // V third
        }
        __syncthreads();

        for (int j = 0; j < KT; j++) {
            const u64* k2 = reinterpret_cast<const u64*>(&Ks[j * HDIM]);
            u64 s0 = 0ull, s1 = 0ull, s2 = 0ull, s3 = 0ull;
            #pragma unroll
            for (int i = 0; i < HDIM / 2; i += 4) {
                s0 = ffma2(q2[i + 0], k2[i + 0], s0);
                s1 = ffma2(q2[i + 1], k2[i + 1], s1);
                s2 = ffma2(q2[i + 2], k2[i + 2], s2);
                s3 = ffma2(q2[i + 3], k2[i + 3], s3);
            }
            float a0, a1, b0, b1, c0, c1, d0, d1;
            upk2(s0, a0, a1); upk2(s1, b0, b1);
            upk2(s2, c0, c1); upk2(s3, d0, d1);
            float s = (a0 + a1) + (b0 + b1) + (c0 + c1) + (d0 + d1);

            float p = __expf(s);
            l += p;
            u64 pp = pk2(p, p);

            const u64* v2 = reinterpret_cast<const u64*>(&Vs[j * HDIM]);
            #pragma unroll
            for (int i = 0; i < HDIM / 2; i++)
                o2[i] = ffma2(pp, v2[i], o2[i]);
        }
        __syncthreads();
    }

    const float inv = 1.0f / l;
    float* outp = g_att + ((size_t)b * SEQ + n) * EMB + hoff;
    #pragma unroll
    for (int d = 0; d < HDIM; d += 4) {
        float x0, x1, x2, x3;
        upk2(o2[d / 2 + 0], x0, x1);
        upk2(o2[d / 2 + 1], x2, x3);
        float4 v;
        v.x = x0 * inv; v.y = x1 * inv; v.z = x2 * inv; v.w = x3 * inv;
        *(float4*)&outp[d] = v;
    }
}

// ---------------------------------------------------------------------------
// Launch: inputs in order x, W_qkv, b_qkv, W_out, b_out
// ---------------------------------------------------------------------------
extern "C" void kernel_launch(void* const* d_in, const int* in_sizes, int n_in,
                              void* d_out, int out_size)
{
    const float* x     = (const float*)d_in[0];
    const float* W_qkv = (const float*)d_in[1];
    const float* b_qkv = (const float*)d_in[2];
    const float* W_out = (const float*)d_in[3];
    const float* b_out = (const float*)d_in[4];
    float*       out   = (float*)d_out;

    float* qkv_ptr = nullptr;
    float* att_ptr = nullptr;
    cudaGetSymbolAddress((void**)&qkv_ptr, g_qkv);
    cudaGetSymbolAddress((void**)&att_ptr, g_att);

    static bool attr_set = false;
    if (!attr_set) {
        cudaFuncSetAttribute(mma_gemm_bias,
                             cudaFuncAttributeMaxDynamicSharedMemorySize, GEMM_SMEM);
        attr_set = true;
    }

    // 1) QKV projection: [4096,1024] @ [1024,3072] + b
    {
        dim3 grid(QKV_COLS / GBN, ROWS / GBM);   // (24, 32)
        mma_gemm_bias<<<grid, 256, GEMM_SMEM>>>(ROWS, QKV_COLS, EMB, x, W_qkv, b_qkv, qkv_ptr);
    }

    // 2) Attention
    {
        dim3 grid(SEQ / QT, BATCH * NHEADS);     // (8, 64)
        attn_kernel<<<grid, QT>>>();
    }

    // 3) Output projection: [4096,1024] @ [1024,1024] + b
    {
        dim3 grid(EMB / GBN, ROWS / GBM);        // (8, 32)
        mma_gemm_bias<<<grid, 256, GEMM_SMEM>>>(ROWS, EMB, EMB, att_ptr, W_out, b_out, out);
    }
}

// round 4
// speedup vs baseline: 3.1243x; 1.8001x over previous
#include <cuda_runtime.h>
#include <cuda_bf16.h>
#include <cstdint>

// Problem constants
#define BATCH     4
#define SEQ       1024
#define EMB       1024
#define NHEADS    16
#define HDIM      64
#define QKV_COLS  (3 * NHEADS * HDIM)   // 3072
#define ROWS      (BATCH * SEQ)         // 4096

// Scratch (allocation-free rule: __device__ globals)
__device__ float g_qkv[ROWS * QKV_COLS];      // 4096 x 3072
__device__ float g_att[ROWS * EMB];           // 4096 x 1024

__device__ __forceinline__ uint32_t f2tf32(float x) {
    uint32_t u;
    asm("cvt.rna.tf32.f32 %0, %1;" : "=r"(u) : "f"(x));
    return u;
}

__device__ __forceinline__ void mma_tf32(float c[4], const uint32_t a[4], const uint32_t b[2]) {
    asm volatile(
        "mma.sync.aligned.m16n8k8.row.col.f32.tf32.tf32.f32 "
        "{%0,%1,%2,%3},{%4,%5,%6,%7},{%8,%9},{%0,%1,%2,%3};"
        : "+f"(c[0]), "+f"(c[1]), "+f"(c[2]), "+f"(c[3])
        : "r"(a[0]), "r"(a[1]), "r"(a[2]), "r"(a[3]), "r"(b[0]), "r"(b[1]));
}

// ===========================================================================
// TF32 mma.sync GEMM with fused bias: C = A[M,K] @ B[K,N] + bias
// CTA tile 128x128x32, 8 warps (2x4), warp tile 64x32 via m16n8k8.
// ===========================================================================
#define GBM 128
#define GBN 128
#define GBK 32
#define ASTRIDE 36
#define BSTRIDE 136
#define GEMM_SMEM ((2*GBM*ASTRIDE + 2*GBK*BSTRIDE) * 4)   // 71680 bytes

__global__ __launch_bounds__(256, 1) void mma_gemm_bias(
    int M, int N, int K,
    const float* __restrict__ A,
    const float* __restrict__ B,
    const float* __restrict__ bias,
    float* __restrict__ C)
{
    extern __shared__ uint32_t sm[];
    uint32_t* As = sm;                         // [2][GBM][ASTRIDE]
    uint32_t* Bs = sm + 2 * GBM * ASTRIDE;     // [2][GBK][BSTRIDE]

    const int t    = threadIdx.x;
    const int lane = t & 31;
    const int warp = t >> 5;
    const int wm   = warp >> 2;   // 0..1
    const int wn   = warp & 3;    // 0..3
    const int grp  = lane >> 2;   // 0..7
    const int qid  = lane & 3;    // 0..3

    const int bm = blockIdx.y * GBM;
    const int bn = blockIdx.x * GBN;

    const int arow = t >> 3;          // 0..31, + p*32
    const int acol = (t & 7) * 4;     // 0..28
    const int brow = t >> 5;          // 0..7,  + p*8
    const int bcol = (t & 31) * 4;    // 0..124

    float4 pa[4], pb[4];

    {
        const float* Ag = A + (size_t)bm * K;
        const float* Bg = B + bn;
        #pragma unroll
        for (int p = 0; p < 4; p++)
            pa[p] = *(const float4*)&Ag[(size_t)(arow + p * 32) * K + acol];
        #pragma unroll
        for (int p = 0; p < 4; p++)
            pb[p] = *(const float4*)&Bg[(size_t)(brow + p * 8) * N + bcol];
    }

    float c[4][4][4];
    #pragma unroll
    for (int mi = 0; mi < 4; mi++)
        #pragma unroll
        for (int ni = 0; ni < 4; ni++)
            #pragma unroll
            for (int r = 0; r < 4; r++)
                c[mi][ni][r] = 0.0f;

    auto sts_tile = [&](int buf) {
        uint32_t* Ab = As + buf * GBM * ASTRIDE;
        uint32_t* Bb = Bs + buf * GBK * BSTRIDE;
        #pragma unroll
        for (int p = 0; p < 4; p++) {
            uint4 v;
            v.x = f2tf32(pa[p].x); v.y = f2tf32(pa[p].y);
            v.z = f2tf32(pa[p].z); v.w = f2tf32(pa[p].w);
            *(uint4*)&Ab[(arow + p * 32) * ASTRIDE + acol] = v;
        }
        #pragma unroll
        for (int p = 0; p < 4; p++) {
            uint4 v;
            v.x = f2tf32(pb[p].x); v.y = f2tf32(pb[p].y);
            v.z = f2tf32(pb[p].z); v.w = f2tf32(pb[p].w);
            *(uint4*)&Bb[(brow + p * 8) * BSTRIDE + bcol] = v;
        }
    };

    sts_tile(0);
    __syncthreads();

    const int NT = K / GBK;
    for (int kt = 0; kt < NT; kt++) {
        const int cur = kt & 1;

        if (kt + 1 < NT) {
            const int k0 = (kt + 1) * GBK;
            const float* Ag = A + (size_t)bm * K + k0;
            const float* Bg = B + (size_t)k0 * N + bn;
            #pragma unroll
            for (int p = 0; p < 4; p++)
                pa[p] = *(const float4*)&Ag[(size_t)(arow + p * 32) * K + acol];
            #pragma unroll
            for (int p = 0; p < 4; p++)
                pb[p] = *(const float4*)&Bg[(size_t)(brow + p * 8) * N + bcol];
        }

        const uint32_t* Ab = As + cur * GBM * ASTRIDE + (wm * 64) * ASTRIDE;
        const uint32_t* Bb = Bs + cur * GBK * BSTRIDE + wn * 32;

        #pragma unroll
        for (int ks = 0; ks < 4; ks++) {
            const int kb = ks * 8;
            uint32_t af[4][4], bf[4][2];
            #pragma unroll
            for (int mi = 0; mi < 4; mi++) {
                const uint32_t* ap = Ab + (mi * 16 + grp) * ASTRIDE + kb + qid;
                af[mi][0] = ap[0];
                af[mi][1] = ap[8 * ASTRIDE];
                af[mi][2] = ap[4];
                af[mi][3] = ap[8 * ASTRIDE + 4];
            }
            #pragma unroll
            for (int ni = 0; ni < 4; ni++) {
                const uint32_t* bp = Bb + (kb + qid) * BSTRIDE + ni * 8 + grp;
                bf[ni][0] = bp[0];
                bf[ni][1] = bp[4 * BSTRIDE];
            }
            #pragma unroll
            for (int mi = 0; mi < 4; mi++)
                #pragma unroll
                for (int ni = 0; ni < 4; ni++)
                    mma_tf32(c[mi][ni], af[mi], bf[ni]);
        }

        if (kt + 1 < NT) sts_tile(cur ^ 1);
        __syncthreads();
    }

    #pragma unroll
    for (int mi = 0; mi < 4; mi++) {
        const int r0 = bm + wm * 64 + mi * 16 + grp;
        #pragma unroll
        for (int ni = 0; ni < 4; ni++) {
            const int col = bn + wn * 32 + ni * 8 + qid * 2;
            float2 bv = *(const float2*)&bias[col];
            float2 v0, v1;
            v0.x = c[mi][ni][0] + bv.x;  v0.y = c[mi][ni][1] + bv.y;
            v1.x = c[mi][ni][2] + bv.x;  v1.y = c[mi][ni][3] + bv.y;
            *(float2*)&C[(size_t)r0 * N + col]       = v0;
            *(float2*)&C[(size_t)(r0 + 8) * N + col] = v1;
        }
    }
}

// ===========================================================================
// Tensor-core flash attention (tf32 mma), per (b,h):
//   O = softmax(Q K^T / 8) V,   scale folded into Q staging (exact, pow2).
// CTA: 128 q rows, 8 warps (16 rows each). Keys streamed in 64-chunks.
// Smem (dynamic): Ks[64][68], Vt[64][68] (V transposed), Ps[128][68]
//   (Ps doubles as Q staging). Strides 68 == 4 (mod 32): fragment LDS
//   bank = 4*grp + qid + const -> conflict-free.
// qkv row layout: [0:1024)=K, [1024:2048)=Q, [2048:3072)=V.
// ===========================================================================
#define AKT 64                    // keys per chunk
#define ASTR 68                   // smem stride (uint32 units)
#define ATT_SMEM ((2 * AKT * ASTR + 128 * ASTR) * 4)   // 69632 bytes

__global__ __launch_bounds__(256, 1) void attn_mma_kernel()
{
    extern __shared__ uint32_t sm[];
    uint32_t* Ks = sm;                  // [64][ASTR]
    uint32_t* Vt = sm + AKT * ASTR;     // [64][ASTR]  (Vt[d][j] = V[j][d])
    uint32_t* Ps = sm + 2 * AKT * ASTR; // [128][ASTR] (also Q staging)

    const int t    = threadIdx.x;
    const int lane = t & 31;
    const int warp = t >> 5;     // 0..7
    const int g8   = lane >> 2;  // 0..7 (group of 4)
    const int qid  = lane & 3;   // 0..3

    const int bh = blockIdx.y;
    const int b  = bh >> 4;
    const int h  = bh & 15;
    const int hoff  = h * HDIM;
    const int qrow0 = blockIdx.x * 128;

    const size_t rowStride = QKV_COLS;
    const float* Kg = g_qkv + (size_t)b * SEQ * rowStride + hoff;              // K third
    const float* Vg = Kg + 2 * EMB;                                            // V third
    const float* Qg = g_qkv + ((size_t)b * SEQ + qrow0) * rowStride + EMB + hoff;

    // ---- stage Q (scaled by 1/8) into Ps: 2 threads per row, 32 cols each ----
    {
        const int j     = t >> 1;          // 0..127
        const int cbase = (t & 1) * 32;    // 0 or 32
        #pragma unroll
        for (int p = 0; p < 8; p++) {
            float4 v = *(const float4*)&Qg[(size_t)j * rowStride + cbase + p * 4];
            uint4 u;
            u.x = f2tf32(v.x * 0.125f); u.y = f2tf32(v.y * 0.125f);
            u.z = f2tf32(v.z * 0.125f); u.w = f2tf32(v.w * 0.125f);
            *(uint4*)&Ps[j * ASTR + cbase + p * 4] = u;
        }
    }
    __syncthreads();

    // ---- load Q fragments into registers (held for whole kernel) ----
    uint32_t qa[8][4];
    {
        const uint32_t* Qw = Ps + (warp * 16 + g8) * ASTR;
        #pragma unroll
        for (int ks = 0; ks < 8; ks++) {
            const uint32_t* ap = Qw + ks * 8 + qid;
            qa[ks][0] = ap[0];
            qa[ks][1] = ap[8 * ASTR];
            qa[ks][2] = ap[4];
            qa[ks][3] = ap[8 * ASTR + 4];
        }
    }
    __syncthreads();   // Q frags read; Ps now reusable for P

    float oc[8][4];
    #pragma unroll
    for (int ni = 0; ni < 8; ni++)
        #pragma unroll
        for (int r = 0; r < 4; r++) oc[ni][r] = 0.0f;
    float lsum0 = 0.0f, lsum1 = 0.0f;

    // staging maps:
    // K: e = t + p*256, j = e>>4, c4 = (e&15)*4  (64 rows x 64 cols)
    // V: vj = t&63 (row), vc = (t>>6)*4, d = vc + p*16 (transpose store)
    const int vj = t & 63;
    const int vc = (t >> 6) * 4;

    float4 kreg[4], vreg[4];
    #pragma unroll
    for (int p = 0; p < 4; p++) {
        int e = t + p * 256;
        int j = e >> 4, c4 = (e & 15) * 4;
        kreg[p] = *(const float4*)&Kg[(size_t)j * rowStride + c4];
    }
    #pragma unroll
    for (int p = 0; p < 4; p++) {
        int d = vc + p * 16;
        vreg[p] = *(const float4*)&Vg[(size_t)vj * rowStride + d];
    }

    for (int kt = 0; kt < SEQ / AKT; kt++) {
        // ---- commit staged chunk to smem (with tf32 cvt) ----
        #pragma unroll
        for (int p = 0; p < 4; p++) {
            int e = t + p * 256;
            int j = e >> 4, c4 = (e & 15) * 4;
            uint4 u;
            u.x = f2tf32(kreg[p].x); u.y = f2tf32(kreg[p].y);
            u.z = f2tf32(kreg[p].z); u.w = f2tf32(kreg[p].w);
            *(uint4*)&Ks[j * ASTR + c4] = u;
        }
        #pragma unroll
        for (int p = 0; p < 4; p++) {
            int d = vc + p * 16;
            Vt[(d + 0) * ASTR + vj] = f2tf32(vreg[p].x);
            Vt[(d + 1) * ASTR + vj] = f2tf32(vreg[p].y);
            Vt[(d + 2) * ASTR + vj] = f2tf32(vreg[p].z);
            Vt[(d + 3) * ASTR + vj] = f2tf32(vreg[p].w);
        }
        __syncthreads();

        // ---- prefetch next chunk ----
        if (kt + 1 < SEQ / AKT) {
            const float* Kn = Kg + (size_t)(kt + 1) * AKT * rowStride;
            const float* Vn = Vg + (size_t)(kt + 1) * AKT * rowStride;
            #pragma unroll
            for (int p = 0; p < 4; p++) {
                int e = t + p * 256;
                int j = e >> 4, c4 = (e & 15) * 4;
                kreg[p] = *(const float4*)&Kn[(size_t)j * rowStride + c4];
            }
            #pragma unroll
            for (int p = 0; p < 4; p++) {
                int d = vc + p * 16;
                vreg[p] = *(const float4*)&Vn[(size_t)vj * rowStride + d];
            }
        }

        // ---- S = Q K^T  (warp: 16 q rows x 64 keys) ----
        float sc[8][4];
        #pragma unroll
        for (int ni = 0; ni < 8; ni++)
            #pragma unroll
            for (int r = 0; r < 4; r++) sc[ni][r] = 0.0f;

        #pragma unroll
        for (int ks = 0; ks < 8; ks++) {
            uint32_t bf[8][2];
            #pragma unroll
            for (int ni = 0; ni < 8; ni++) {
                const uint32_t* bp = Ks + (ni * 8 + g8) * ASTR + ks * 8 + qid;
                bf[ni][0] = bp[0];
                bf[ni][1] = bp[4];
            }
            #pragma unroll
            for (int ni = 0; ni < 8; ni++)
                mma_tf32(sc[ni], qa[ks], bf[ni]);
        }

        // ---- P = exp(S); row-sum; store P (tf32) to Ps ----
        uint32_t* Pw = Ps + (warp * 16 + g8) * ASTR;
        #pragma unroll
        for (int ni = 0; ni < 8; ni++) {
            float p0 = __expf(sc[ni][0]);
            float p1 = __expf(sc[ni][1]);
            float p2 = __expf(sc[ni][2]);
            float p3 = __expf(sc[ni][3]);
            lsum0 += p0 + p1;
            lsum1 += p2 + p3;
            uint2 u0, u1;
            u0.x = f2tf32(p0); u0.y = f2tf32(p1);
            u1.x = f2tf32(p2); u1.y = f2tf32(p3);
            *(uint2*)&Pw[ni * 8 + qid * 2]            = u0;
            *(uint2*)&Pw[8 * ASTR + ni * 8 + qid * 2] = u1;
        }
        __syncwarp();   // P exchanged only within this warp's 16 rows

        // ---- O += P V  (A frags from Ps, B frags from Vt) ----
        #pragma unroll
        for (int ks = 0; ks < 8; ks++) {
            uint32_t af[4];
            const uint32_t* ap = Pw + ks * 8 + qid;
            af[0] = ap[0];
            af[1] = ap[8 * ASTR];
            af[2] = ap[4];
            af[3] = ap[8 * ASTR + 4];
            uint32_t bf[8][2];
            #pragma unroll
            for (int ni = 0; ni < 8; ni++) {
                const uint32_t* bp = Vt + (ni * 8 + g8) * ASTR + ks * 8 + qid;
                bf[ni][0] = bp[0];
                bf[ni][1] = bp[4];
            }
            #pragma unroll
            for (int ni = 0; ni < 8; ni++)
                mma_tf32(oc[ni], af, bf[ni]);
        }
        __syncthreads();   // done reading Ks/Vt; safe to overwrite next iter
    }

    // ---- normalize and write out ----
    float l0 = lsum0, l1 = lsum1;
    #pragma unroll
    for (int m = 1; m < 4; m <<= 1) {
        l0 += __shfl_xor_sync(0xffffffffu, l0, m);
        l1 += __shfl_xor_sync(0xffffffffu, l1, m);
    }
    const float inv0 = 1.0f / l0;
    const float inv1 = 1.0f / l1;

    const int r0 = qrow0 + warp * 16 + g8;
    float* O0 = g_att + ((size_t)b * SEQ + r0) * EMB + hoff;
    float* O1 = O0 + 8 * EMB;
    #pragma unroll
    for (int ni = 0; ni < 8; ni++) {
        const int col = ni * 8 + qid * 2;
        float2 v0, v1;
        v0.x = oc[ni][0] * inv0;  v0.y = oc[ni][1] * inv0;
        v1.x = oc[ni][2] * inv1;  v1.y = oc[ni][3] * inv1;
        *(float2*)&O0[col] = v0;
        *(float2*)&O1[col] = v1;
    }
}

// ---------------------------------------------------------------------------
// Launch: inputs in order x, W_qkv, b_qkv, W_out, b_out
// ---------------------------------------------------------------------------
extern "C" void kernel_launch(void* const* d_in, const int* in_sizes, int n_in,
                              void* d_out, int out_size)
{
    const float* x     = (const float*)d_in[0];
    const float* W_qkv = (const float*)d_in[1];
    const float* b_qkv = (const float*)d_in[2];
    const float* W_out = (const float*)d_in[3];
    const float* b_out = (const float*)d_in[4];
    float*       out   = (float*)d_out;

    float* qkv_ptr = nullptr;
    float* att_ptr = nullptr;
    cudaGetSymbolAddress((void**)&qkv_ptr, g_qkv);
    cudaGetSymbolAddress((void**)&att_ptr, g_att);

    static bool attr_set = false;
    if (!attr_set) {
        cudaFuncSetAttribute(mma_gemm_bias,
                             cudaFuncAttributeMaxDynamicSharedMemorySize, GEMM_SMEM);
        cudaFuncSetAttribute(attn_mma_kernel,
                             cudaFuncAttributeMaxDynamicSharedMemorySize, ATT_SMEM);
        attr_set = true;
    }

    // 1) QKV projection: [4096,1024] @ [1024,3072] + b
    {
        dim3 grid(QKV_COLS / GBN, ROWS / GBM);   // (24, 32)
        mma_gemm_bias<<<grid, 256, GEMM_SMEM>>>(ROWS, QKV_COLS, EMB, x, W_qkv, b_qkv, qkv_ptr);
    }

    // 2) Attention (tensor-core)
    {
        dim3 grid(SEQ / 128, BATCH * NHEADS);    // (8, 64)
        attn_mma_kernel<<<grid, 256, ATT_SMEM>>>();
    }

    // 3) Output projection: [4096,1024] @ [1024,1024] + b
    {
        dim3 grid(EMB / GBN, ROWS / GBM);        // (8, 32)
        mma_gemm_bias<<<grid, 256, GEMM_SMEM>>>(ROWS, EMB, EMB, att_ptr, W_out, b_out, out);
    }
}

// round 5
// speedup vs baseline: 3.6590x; 1.1711x over previous
#include <cuda_runtime.h>
#include <cuda_bf16.h>
#include <cstdint>

// Problem constants
#define BATCH     4
#define SEQ       1024
#define EMB       1024
#define NHEADS    16
#define HDIM      64
#define QKV_COLS  (3 * NHEADS * HDIM)   // 3072
#define ROWS      (BATCH * SEQ)         // 4096

// Scratch (allocation-free rule: __device__ globals)
__device__ float g_qkv[ROWS * QKV_COLS];      // 4096 x 3072
__device__ float g_att[ROWS * EMB];           // 4096 x 1024

__device__ __forceinline__ uint32_t f2tf32(float x) {
    uint32_t u;
    asm("cvt.rna.tf32.f32 %0, %1;" : "=r"(u) : "f"(x));
    return u;
}

__device__ __forceinline__ void mma_tf32(float c[4], const uint32_t a[4], const uint32_t b[2]) {
    asm volatile(
        "mma.sync.aligned.m16n8k8.row.col.f32.tf32.tf32.f32 "
        "{%0,%1,%2,%3},{%4,%5,%6,%7},{%8,%9},{%0,%1,%2,%3};"
        : "+f"(c[0]), "+f"(c[1]), "+f"(c[2]), "+f"(c[3])
        : "r"(a[0]), "r"(a[1]), "r"(a[2]), "r"(a[3]), "r"(b[0]), "r"(b[1]));
}

__device__ __forceinline__ void cp_async16(uint32_t dst, const void* src) {
    asm volatile("cp.async.cg.shared.global [%0], [%1], 16;" :: "r"(dst), "l"(src));
}
__device__ __forceinline__ void cp_commit() {
    asm volatile("cp.async.commit_group;");
}
template <int N>
__device__ __forceinline__ void cp_wait() {
    asm volatile("cp.async.wait_group %0;" :: "n"(N));
}

// ===========================================================================
// TF32 mma.sync GEMM, fused bias. CTA 128x128x32, 8 warps, warp tile 64x32.
// cp.async 2-stage pipeline (raw fp32 in smem); cvt.rna.tf32 at fragment load.
// 2 CTAs/SM via launch_bounds.
// ===========================================================================
#define GBM 128
#define GBN 128
#define GBK 32
#define ASTRIDE 36
#define BSTRIDE 136
#define ABUF (GBM * ASTRIDE)     // floats per A buffer
#define BBUF (GBK * BSTRIDE)     // floats per B buffer
#define GEMM_SMEM ((2 * ABUF + 2 * BBUF) * 4)   // 71680 bytes

__global__ __launch_bounds__(256, 2) void mma_gemm_bias(
    int M, int N, int K,
    const float* __restrict__ A,
    const float* __restrict__ B,
    const float* __restrict__ bias,
    float* __restrict__ C)
{
    extern __shared__ float smf[];
    float* As = smf;                 // [2][GBM][ASTRIDE]
    float* Bs = smf + 2 * ABUF;      // [2][GBK][BSTRIDE]
    const uint32_t sAs = (uint32_t)__cvta_generic_to_shared(As);
    const uint32_t sBs = (uint32_t)__cvta_generic_to_shared(Bs);

    const int t    = threadIdx.x;
    const int lane = t & 31;
    const int warp = t >> 5;
    const int wm   = warp >> 2;   // 0..1
    const int wn   = warp & 3;    // 0..3
    const int grp  = lane >> 2;   // 0..7
    const int qid  = lane & 3;    // 0..3

    const int bm = blockIdx.y * GBM;
    const int bn = blockIdx.x * GBN;

    const int arow = t >> 3;          // 0..31, + p*32
    const int acol = (t & 7) * 4;     // 0..28
    const int brow = t >> 5;          // 0..7,  + p*8
    const int bcol = (t & 31) * 4;    // 0..124

    // async tile issue
    auto issue = [&](int buf, int kt) {
        const float* Ag = A + (size_t)bm * K + kt * GBK;
        const float* Bg = B + (size_t)(kt * GBK) * N + bn;
        #pragma unroll
        for (int p = 0; p < 4; p++) {
            int r = arow + p * 32;
            cp_async16(sAs + (uint32_t)(buf * ABUF + r * ASTRIDE + acol) * 4,
                       &Ag[(size_t)r * K + acol]);
        }
        #pragma unroll
        for (int p = 0; p < 4; p++) {
            int r = brow + p * 8;
            cp_async16(sBs + (uint32_t)(buf * BBUF + r * BSTRIDE + bcol) * 4,
                       &Bg[(size_t)r * N + bcol]);
        }
    };

    float c[4][4][4];
    #pragma unroll
    for (int mi = 0; mi < 4; mi++)
        #pragma unroll
        for (int ni = 0; ni < 4; ni++)
            #pragma unroll
            for (int r = 0; r < 4; r++)
                c[mi][ni][r] = 0.0f;

    issue(0, 0);
    cp_commit();

    const int NT = K / GBK;
    for (int kt = 0; kt < NT; kt++) {
        const int cur = kt & 1;
        if (kt + 1 < NT) {
            issue(cur ^ 1, kt + 1);
            cp_commit();
            cp_wait<1>();
        } else {
            cp_wait<0>();
        }
        __syncthreads();

        const float* Ab = As + cur * ABUF + (wm * 64) * ASTRIDE;
        const float* Bb = Bs + cur * BBUF + wn * 32;

        #pragma unroll
        for (int ks = 0; ks < 4; ks++) {
            const int kb = ks * 8;
            uint32_t af[4][4], bf[4][2];
            #pragma unroll
            for (int mi = 0; mi < 4; mi++) {
                const float* ap = Ab + (mi * 16 + grp) * ASTRIDE + kb + qid;
                af[mi][0] = f2tf32(ap[0]);
                af[mi][1] = f2tf32(ap[8 * ASTRIDE]);
                af[mi][2] = f2tf32(ap[4]);
                af[mi][3] = f2tf32(ap[8 * ASTRIDE + 4]);
            }
            #pragma unroll
            for (int ni = 0; ni < 4; ni++) {
                const float* bp = Bb + (kb + qid) * BSTRIDE + ni * 8 + grp;
                bf[ni][0] = f2tf32(bp[0]);
                bf[ni][1] = f2tf32(bp[4 * BSTRIDE]);
            }
            #pragma unroll
            for (int mi = 0; mi < 4; mi++)
                #pragma unroll
                for (int ni = 0; ni < 4; ni++)
                    mma_tf32(c[mi][ni], af[mi], bf[ni]);
        }
        __syncthreads();
    }

    #pragma unroll
    for (int mi = 0; mi < 4; mi++) {
        const int r0 = bm + wm * 64 + mi * 16 + grp;
        #pragma unroll
        for (int ni = 0; ni < 4; ni++) {
            const int col = bn + wn * 32 + ni * 8 + qid * 2;
            float2 bv = *(const float2*)&bias[col];
            float2 v0, v1;
            v0.x = c[mi][ni][0] + bv.x;  v0.y = c[mi][ni][1] + bv.y;
            v1.x = c[mi][ni][2] + bv.x;  v1.y = c[mi][ni][3] + bv.y;
            *(float2*)&C[(size_t)r0 * N + col]       = v0;
            *(float2*)&C[(size_t)(r0 + 8) * N + col] = v1;
        }
    }
}

// ===========================================================================
// Tensor-core flash attention (tf32 mma), per (b,h):
//   O = softmax(Q K^T / 8) V, scale folded into Q staging (exact pow2).
// CTA: 128 q rows, 8 warps. Keys streamed in 64-chunks, no reg prefetch
// (2 CTAs/SM provide the overlap instead).
// ===========================================================================
#define AKT 64
#define ASTR 68
#define ATT_SMEM ((2 * AKT * ASTR + 128 * ASTR) * 4)   // 69632 bytes

__global__ __launch_bounds__(256, 2) void attn_mma_kernel()
{
    extern __shared__ uint32_t sm[];
    uint32_t* Ks = sm;                  // [64][ASTR]
    uint32_t* Vt = sm + AKT * ASTR;     // [64][ASTR]  (Vt[d][j] = V[j][d])
    uint32_t* Ps = sm + 2 * AKT * ASTR; // [128][ASTR] (also Q staging)

    const int t    = threadIdx.x;
    const int lane = t & 31;
    const int warp = t >> 5;     // 0..7
    const int g8   = lane >> 2;  // 0..7
    const int qid  = lane & 3;   // 0..3

    const int bh = blockIdx.y;
    const int b  = bh >> 4;
    const int h  = bh & 15;
    const int hoff  = h * HDIM;
    const int qrow0 = blockIdx.x * 128;

    const size_t rowStride = QKV_COLS;
    const float* Kg = g_qkv + (size_t)b * SEQ * rowStride + hoff;              // K third
    const float* Vg = Kg + 2 * EMB;                                            // V third
    const float* Qg = g_qkv + ((size_t)b * SEQ + qrow0) * rowStride + EMB + hoff;

    // ---- stage Q (scaled by 1/8) into Ps: 2 threads per row, 32 cols each ----
    {
        const int j     = t >> 1;
        const int cbase = (t & 1) * 32;
        #pragma unroll
        for (int p = 0; p < 8; p++) {
            float4 v = *(const float4*)&Qg[(size_t)j * rowStride + cbase + p * 4];
            uint4 u;
            u.x = f2tf32(v.x * 0.125f); u.y = f2tf32(v.y * 0.125f);
            u.z = f2tf32(v.z * 0.125f); u.w = f2tf32(v.w * 0.125f);
            *(uint4*)&Ps[j * ASTR + cbase + p * 4] = u;
        }
    }
    __syncthreads();

    // ---- load Q fragments into registers ----
    uint32_t qa[8][4];
    {
        const uint32_t* Qw = Ps + (warp * 16 + g8) * ASTR;
        #pragma unroll
        for (int ks = 0; ks < 8; ks++) {
            const uint32_t* ap = Qw + ks * 8 + qid;
            qa[ks][0] = ap[0];
            qa[ks][1] = ap[8 * ASTR];
            qa[ks][2] = ap[4];
            qa[ks][3] = ap[8 * ASTR + 4];
        }
    }
    __syncthreads();

    float oc[8][4];
    #pragma unroll
    for (int ni = 0; ni < 8; ni++)
        #pragma unroll
        for (int r = 0; r < 4; r++) oc[ni][r] = 0.0f;
    float lsum0 = 0.0f, lsum1 = 0.0f;

    const int vj = t & 63;
    const int vc = (t >> 6) * 4;

    for (int kt = 0; kt < SEQ / AKT; kt++) {
        const float* Kn = Kg + (size_t)kt * AKT * rowStride;
        const float* Vn = Vg + (size_t)kt * AKT * rowStride;
        #pragma unroll
        for (int p = 0; p < 4; p++) {
            int e = t + p * 256;
            int j = e >> 4, c4 = (e & 15) * 4;
            float4 v = *(const float4*)&Kn[(size_t)j * rowStride + c4];
            uint4 u;
            u.x = f2tf32(v.x); u.y = f2tf32(v.y);
            u.z = f2tf32(v.z); u.w = f2tf32(v.w);
            *(uint4*)&Ks[j * ASTR + c4] = u;
        }
        #pragma unroll
        for (int p = 0; p < 4; p++) {
            int d = vc + p * 16;
            float4 v = *(const float4*)&Vn[(size_t)vj * rowStride + d];
            Vt[(d + 0) * ASTR + vj] = f2tf32(v.x);
            Vt[(d + 1) * ASTR + vj] = f2tf32(v.y);
            Vt[(d + 2) * ASTR + vj] = f2tf32(v.z);
            Vt[(d + 3) * ASTR + vj] = f2tf32(v.w);
        }
        __syncthreads();

        // ---- S = Q K^T ----
        float sc[8][4];
        #pragma unroll
        for (int ni = 0; ni < 8; ni++)
            #pragma unroll
            for (int r = 0; r < 4; r++) sc[ni][r] = 0.0f;

        #pragma unroll
        for (int ks = 0; ks < 8; ks++) {
            uint32_t bf[8][2];
            #pragma unroll
            for (int ni = 0; ni < 8; ni++) {
                const uint32_t* bp = Ks + (ni * 8 + g8) * ASTR + ks * 8 + qid;
                bf[ni][0] = bp[0];
                bf[ni][1] = bp[4];
            }
            #pragma unroll
            for (int ni = 0; ni < 8; ni++)
                mma_tf32(sc[ni], qa[ks], bf[ni]);
        }

        // ---- P = exp(S); row-sum; store P (tf32) ----
        uint32_t* Pw = Ps + (warp * 16 + g8) * ASTR;
        #pragma unroll
        for (int ni = 0; ni < 8; ni++) {
            float p0 = __expf(sc[ni][0]);
            float p1 = __expf(sc[ni][1]);
            float p2 = __expf(sc[ni][2]);
            float p3 = __expf(sc[ni][3]);
            lsum0 += p0 + p1;
            lsum1 += p2 + p3;
            uint2 u0, u1;
            u0.x = f2tf32(p0); u0.y = f2tf32(p1);
            u1.x = f2tf32(p2); u1.y = f2tf32(p3);
            *(uint2*)&Pw[ni * 8 + qid * 2]            = u0;
            *(uint2*)&Pw[8 * ASTR + ni * 8 + qid * 2] = u1;
        }
        __syncwarp();

        // ---- O += P V ----
        #pragma unroll
        for (int ks = 0; ks < 8; ks++) {
            uint32_t af[4];
            const uint32_t* ap = Pw + ks * 8 + qid;
            af[0] = ap[0];
            af[1] = ap[8 * ASTR];
            af[2] = ap[4];
            af[3] = ap[8 * ASTR + 4];
            uint32_t bf[8][2];
            #pragma unroll
            for (int ni = 0; ni < 8; ni++) {
                const uint32_t* bp = Vt + (ni * 8 + g8) * ASTR + ks * 8 + qid;
                bf[ni][0] = bp[0];
                bf[ni][1] = bp[4];
            }
            #pragma unroll
            for (int ni = 0; ni < 8; ni++)
                mma_tf32(oc[ni], af, bf[ni]);
        }
        __syncthreads();
    }

    // ---- normalize and write out ----
    float l0 = lsum0, l1 = lsum1;
    #pragma unroll
    for (int m = 1; m < 4; m <<= 1) {
        l0 += __shfl_xor_sync(0xffffffffu, l0, m);
        l1 += __shfl_xor_sync(0xffffffffu, l1, m);
    }
    const float inv0 = 1.0f / l0;
    const float inv1 = 1.0f / l1;

    const int r0 = qrow0 + warp * 16 + g8;
    float* O0 = g_att + ((size_t)b * SEQ + r0) * EMB + hoff;
    float* O1 = O0 + 8 * EMB;
    #pragma unroll
    for (int ni = 0; ni < 8; ni++) {
        const int col = ni * 8 + qid * 2;
        float2 v0, v1;
        v0.x = oc[ni][0] * inv0;  v0.y = oc[ni][1] * inv0;
        v1.x = oc[ni][2] * inv1;  v1.y = oc[ni][3] * inv1;
        *(float2*)&O0[col] = v0;
        *(float2*)&O1[col] = v1;
    }
}

// ---------------------------------------------------------------------------
// Launch: inputs in order x, W_qkv, b_qkv, W_out, b_out
// ---------------------------------------------------------------------------
extern "C" void kernel_launch(void* const* d_in, const int* in_sizes, int n_in,
                              void* d_out, int out_size)
{
    const float* x     = (const float*)d_in[0];
    const float* W_qkv = (const float*)d_in[1];
    const float* b_qkv = (const float*)d_in[2];
    const float* W_out = (const float*)d_in[3];
    const float* b_out = (const float*)d_in[4];
    float*       out   = (float*)d_out;

    float* qkv_ptr = nullptr;
    float* att_ptr = nullptr;
    cudaGetSymbolAddress((void**)&qkv_ptr, g_qkv);
    cudaGetSymbolAddress((void**)&att_ptr, g_att);

    static bool attr_set = false;
    if (!attr_set) {
        cudaFuncSetAttribute(mma_gemm_bias,
                             cudaFuncAttributeMaxDynamicSharedMemorySize, GEMM_SMEM);
        cudaFuncSetAttribute(attn_mma_kernel,
                             cudaFuncAttributeMaxDynamicSharedMemorySize, ATT_SMEM);
        attr_set = true;
    }

    // 1) QKV projection: [4096,1024] @ [1024,3072] + b
    {
        dim3 grid(QKV_COLS / GBN, ROWS / GBM);   // (24, 32)
        mma_gemm_bias<<<grid, 256, GEMM_SMEM>>>(ROWS, QKV_COLS, EMB, x, W_qkv, b_qkv, qkv_ptr);
    }

    // 2) Attention (tensor-core)
    {
        dim3 grid(SEQ / 128, BATCH * NHEADS);    // (8, 64)
        attn_mma_kernel<<<grid, 256, ATT_SMEM>>>();
    }

    // 3) Output projection: [4096,1024] @ [1024,1024] + b
    {
        dim3 grid(EMB / GBN, ROWS / GBM);        // (8, 32)
        mma_gemm_bias<<<grid, 256, GEMM_SMEM>>>(ROWS, EMB, EMB, att_ptr, W_out, b_out, out);
    }
}